// round 1
// baseline (speedup 1.0000x reference)
#include <cuda_runtime.h>
#include <cuda_bf16.h>
#include <math.h>

// Problem constants
#define P_NUM 64
#define B_NUM 32
#define D_DIM 512
#define H_DIM 2048
#define E_NUM 16
#define N_TOK (P_NUM * B_NUM)        // 2048 tokens
#define N_ROWS (N_TOK * 2)           // 4096 assignment rows (2 slots per token)

// ---- device scratch (no allocations allowed) ----
__device__ int   g_cnt[E_NUM];
__device__ int   g_tok [E_NUM][N_TOK];   // token id per bucket entry
__device__ int   g_row [E_NUM][N_TOK];   // 2*t + slot
__device__ float g_gate[E_NUM][N_TOK];   // softmax gate weight
__device__ float g_H[(size_t)N_ROWS * H_DIM]; // 32 MB hidden scratch
__device__ float g_Y[(size_t)N_ROWS * D_DIM]; // 8 MB per-slot output

// ---------------------------------------------------------------------------
__global__ void reset_kernel() {
    if (threadIdx.x < E_NUM) g_cnt[threadIdx.x] = 0;
}

// ---------------------------------------------------------------------------
// One warp per token: values = x . w_gate  -> top-2 -> softmax -> bucket.
__global__ void gating_kernel(const float* __restrict__ x,
                              const float* __restrict__ wg) {
    int t = blockIdx.x;
    __shared__ float xs[D_DIM];
    __shared__ float vals[E_NUM];
    int tid = threadIdx.x; // blockDim = 32

    const float4* xr = reinterpret_cast<const float4*>(x + (size_t)t * D_DIM);
    float4* xs4 = reinterpret_cast<float4*>(xs);
    #pragma unroll
    for (int i = tid; i < D_DIM / 4; i += 32) xs4[i] = xr[i];
    __syncwarp();

    if (tid < E_NUM) {
        float acc = 0.f;
        #pragma unroll 8
        for (int d = 0; d < D_DIM; d++) acc += xs[d] * wg[d * E_NUM + tid];
        vals[tid] = acc;
    }
    __syncwarp();

    if (tid == 0) {
        float v1 = -INFINITY, v2 = -INFINITY;
        int i1 = 0, i2 = 0;
        #pragma unroll
        for (int e = 0; e < E_NUM; e++) {
            float v = vals[e];
            if (v > v1) { v2 = v1; i2 = i1; v1 = v; i1 = e; }
            else if (v > v2) { v2 = v; i2 = e; }
        }
        // softmax over {v1, v2} (v1 >= v2)
        float ex = __expf(v2 - v1);
        float inv = 1.f / (1.f + ex);
        float gA = inv;          // weight for top-1
        float gB = ex * inv;     // weight for top-2

        int p1 = atomicAdd(&g_cnt[i1], 1);
        g_tok[i1][p1] = t; g_row[i1][p1] = 2 * t;     g_gate[i1][p1] = gA;
        int p2 = atomicAdd(&g_cnt[i2], 1);
        g_tok[i2][p2] = t; g_row[i2][p2] = 2 * t + 1; g_gate[i2][p2] = gB;
    }
}

// ---------------------------------------------------------------------------
// Tiled fp32 grouped GEMM, stage 1: H = relu(Xg @ W1[e] + b1[e])
// Tiles: BM=128, BN=64, BK=16; 256 threads; 8x4 micro-tile.
#define BM 128
#define BN 64
#define BK 16

__global__ __launch_bounds__(256)
void gemm1_kernel(const float* __restrict__ x,
                  const float* __restrict__ w1,
                  const float* __restrict__ b1) {
    const int e   = blockIdx.z;
    const int cnt = g_cnt[e];
    const int m0  = blockIdx.y * BM;
    if (m0 >= cnt) return;
    const int n0  = blockIdx.x * BN;

    __shared__ float As[BK][BM];
    __shared__ float Bs[BK][BN];

    const int tid = threadIdx.x;
    const int tx  = tid & 15;
    const int ty  = tid >> 4;

    const float* Bbase = w1 + (size_t)e * D_DIM * H_DIM;

    // A load mapping: each thread loads 8 floats (2 float4) of one gathered row
    const int ar  = tid >> 1;
    const int ac4 = (tid & 1) * 8;
    const int gm  = m0 + ar;
    const float* arow = (gm < cnt) ? (x + (size_t)g_tok[e][gm] * D_DIM) : nullptr;

    // B load mapping: one float4 per thread
    const int bk = tid >> 4;
    const int bn = (tid & 15) * 4;

    float acc[8][4];
    #pragma unroll
    for (int i = 0; i < 8; i++)
        #pragma unroll
        for (int j = 0; j < 4; j++) acc[i][j] = 0.f;

    for (int k0 = 0; k0 < D_DIM; k0 += BK) {
        float4 a0 = make_float4(0.f, 0.f, 0.f, 0.f), a1 = a0;
        if (arow) {
            a0 = *reinterpret_cast<const float4*>(arow + k0 + ac4);
            a1 = *reinterpret_cast<const float4*>(arow + k0 + ac4 + 4);
        }
        As[ac4 + 0][ar] = a0.x; As[ac4 + 1][ar] = a0.y;
        As[ac4 + 2][ar] = a0.z; As[ac4 + 3][ar] = a0.w;
        As[ac4 + 4][ar] = a1.x; As[ac4 + 5][ar] = a1.y;
        As[ac4 + 6][ar] = a1.z; As[ac4 + 7][ar] = a1.w;

        float4 bv = *reinterpret_cast<const float4*>(
            Bbase + (size_t)(k0 + bk) * H_DIM + n0 + bn);
        *reinterpret_cast<float4*>(&Bs[bk][bn]) = bv;
        __syncthreads();

        #pragma unroll
        for (int kk = 0; kk < BK; kk++) {
            float4 af0 = *reinterpret_cast<float4*>(&As[kk][ty * 8]);
            float4 af1 = *reinterpret_cast<float4*>(&As[kk][ty * 8 + 4]);
            float4 bf  = *reinterpret_cast<float4*>(&Bs[kk][tx * 4]);
            float a[8] = {af0.x, af0.y, af0.z, af0.w, af1.x, af1.y, af1.z, af1.w};
            float b[4] = {bf.x, bf.y, bf.z, bf.w};
            #pragma unroll
            for (int i = 0; i < 8; i++)
                #pragma unroll
                for (int j = 0; j < 4; j++) acc[i][j] += a[i] * b[j];
        }
        __syncthreads();
    }

    float4 bias = *reinterpret_cast<const float4*>(
        b1 + (size_t)e * H_DIM + n0 + tx * 4);
    #pragma unroll
    for (int i = 0; i < 8; i++) {
        int m = m0 + ty * 8 + i;
        if (m >= cnt) continue;
        int row = g_row[e][m];
        float4 v;
        v.x = fmaxf(acc[i][0] + bias.x, 0.f);
        v.y = fmaxf(acc[i][1] + bias.y, 0.f);
        v.z = fmaxf(acc[i][2] + bias.z, 0.f);
        v.w = fmaxf(acc[i][3] + bias.w, 0.f);
        *reinterpret_cast<float4*>(g_H + (size_t)row * H_DIM + n0 + tx * 4) = v;
    }
}

// ---------------------------------------------------------------------------
// Stage 2: Y = gate * (Hg @ W2[e] + b2[e])
__global__ __launch_bounds__(256)
void gemm2_kernel(const float* __restrict__ w2,
                  const float* __restrict__ b2) {
    const int e   = blockIdx.z;
    const int cnt = g_cnt[e];
    const int m0  = blockIdx.y * BM;
    if (m0 >= cnt) return;
    const int n0  = blockIdx.x * BN;

    __shared__ float As[BK][BM];
    __shared__ float Bs[BK][BN];

    const int tid = threadIdx.x;
    const int tx  = tid & 15;
    const int ty  = tid >> 4;

    const float* Bbase = w2 + (size_t)e * H_DIM * D_DIM;

    const int ar  = tid >> 1;
    const int ac4 = (tid & 1) * 8;
    const int gm  = m0 + ar;
    const float* arow = (gm < cnt) ? (g_H + (size_t)g_row[e][gm] * H_DIM) : nullptr;

    const int bk = tid >> 4;
    const int bn = (tid & 15) * 4;

    float acc[8][4];
    #pragma unroll
    for (int i = 0; i < 8; i++)
        #pragma unroll
        for (int j = 0; j < 4; j++) acc[i][j] = 0.f;

    for (int k0 = 0; k0 < H_DIM; k0 += BK) {
        float4 a0 = make_float4(0.f, 0.f, 0.f, 0.f), a1 = a0;
        if (arow) {
            a0 = *reinterpret_cast<const float4*>(arow + k0 + ac4);
            a1 = *reinterpret_cast<const float4*>(arow + k0 + ac4 + 4);
        }
        As[ac4 + 0][ar] = a0.x; As[ac4 + 1][ar] = a0.y;
        As[ac4 + 2][ar] = a0.z; As[ac4 + 3][ar] = a0.w;
        As[ac4 + 4][ar] = a1.x; As[ac4 + 5][ar] = a1.y;
        As[ac4 + 6][ar] = a1.z; As[ac4 + 7][ar] = a1.w;

        float4 bv = *reinterpret_cast<const float4*>(
            Bbase + (size_t)(k0 + bk) * D_DIM + n0 + bn);
        *reinterpret_cast<float4*>(&Bs[bk][bn]) = bv;
        __syncthreads();

        #pragma unroll
        for (int kk = 0; kk < BK; kk++) {
            float4 af0 = *reinterpret_cast<float4*>(&As[kk][ty * 8]);
            float4 af1 = *reinterpret_cast<float4*>(&As[kk][ty * 8 + 4]);
            float4 bf  = *reinterpret_cast<float4*>(&Bs[kk][tx * 4]);
            float a[8] = {af0.x, af0.y, af0.z, af0.w, af1.x, af1.y, af1.z, af1.w};
            float b[4] = {bf.x, bf.y, bf.z, bf.w};
            #pragma unroll
            for (int i = 0; i < 8; i++)
                #pragma unroll
                for (int j = 0; j < 4; j++) acc[i][j] += a[i] * b[j];
        }
        __syncthreads();
    }

    float4 bias = *reinterpret_cast<const float4*>(
        b2 + (size_t)e * D_DIM + n0 + tx * 4);
    #pragma unroll
    for (int i = 0; i < 8; i++) {
        int m = m0 + ty * 8 + i;
        if (m >= cnt) continue;
        int   row = g_row[e][m];
        float g   = g_gate[e][m];
        float4 v;
        v.x = g * (acc[i][0] + bias.x);
        v.y = g * (acc[i][1] + bias.y);
        v.z = g * (acc[i][2] + bias.z);
        v.w = g * (acc[i][3] + bias.w);
        *reinterpret_cast<float4*>(g_Y + (size_t)row * D_DIM + n0 + tx * 4) = v;
    }
}

// ---------------------------------------------------------------------------
// out[t][d] = Y[2t][d] + Y[2t+1][d]   (deterministic, no atomics)
__global__ void combine_kernel(float* __restrict__ out) {
    int i = blockIdx.x * blockDim.x + threadIdx.x; // float4 index
    if (i >= N_TOK * D_DIM / 4) return;
    int t  = i / (D_DIM / 4);
    int d4 = i % (D_DIM / 4);
    const float4* y0 = reinterpret_cast<const float4*>(g_Y + (size_t)(2 * t)     * D_DIM) + d4;
    const float4* y1 = reinterpret_cast<const float4*>(g_Y + (size_t)(2 * t + 1) * D_DIM) + d4;
    float4 a = *y0, b = *y1;
    float4 r = make_float4(a.x + b.x, a.y + b.y, a.z + b.z, a.w + b.w);
    reinterpret_cast<float4*>(out)[i] = r;
}

// ---------------------------------------------------------------------------
// aux = 0.01 * var(importance, ddof=1) / (mean(importance)^2 + 1e-10)
__global__ void aux_kernel(float* __restrict__ out, int out_size) {
    __shared__ float imp[E_NUM];
    int w = threadIdx.x >> 5, lane = threadIdx.x & 31; // 512 threads = 16 warps
    int cnt = g_cnt[w];
    float s = 0.f;
    for (int i = lane; i < cnt; i += 32) s += g_gate[w][i];
    #pragma unroll
    for (int off = 16; off > 0; off >>= 1) s += __shfl_down_sync(0xffffffffu, s, off);
    if (lane == 0) imp[w] = s;
    __syncthreads();
    if (threadIdx.x == 0) {
        float mean = 0.f;
        #pragma unroll
        for (int e = 0; e < E_NUM; e++) mean += imp[e];
        mean *= (1.f / E_NUM);
        float var = 0.f;
        #pragma unroll
        for (int e = 0; e < E_NUM; e++) {
            float d = imp[e] - mean; var += d * d;
        }
        var *= (1.f / (E_NUM - 1));
        float aux = 0.01f * var / (mean * mean + 1e-10f);
        if (out_size > N_TOK * D_DIM) out[out_size - 1] = aux;
    }
}

// ---------------------------------------------------------------------------
extern "C" void kernel_launch(void* const* d_in, const int* in_sizes, int n_in,
                              void* d_out, int out_size) {
    const float* x  = (const float*)d_in[0];
    const float* wg = (const float*)d_in[1];
    const float* w1 = (const float*)d_in[2];
    const float* b1 = (const float*)d_in[3];
    const float* w2 = (const float*)d_in[4];
    const float* b2 = (const float*)d_in[5];
    float* out = (float*)d_out;

    reset_kernel<<<1, 32>>>();
    gating_kernel<<<N_TOK, 32>>>(x, wg);
    // GEMM1: N=2048 -> 32 n-tiles; worst-case 16 m-tiles (cnt up to 2048); 16 experts
    gemm1_kernel<<<dim3(H_DIM / BN, N_TOK / BM, E_NUM), 256>>>(x, w1, b1);
    // GEMM2: N=512 -> 8 n-tiles
    gemm2_kernel<<<dim3(D_DIM / BN, N_TOK / BM, E_NUM), 256>>>(w2, b2);
    combine_kernel<<<(N_TOK * D_DIM / 4 + 255) / 256, 256>>>(out);
    aux_kernel<<<1, 512>>>(out, out_size);
}